// round 12
// baseline (speedup 1.0000x reference)
#include <cuda_runtime.h>
#include <cstdint>

#define BB 2048
#define TT 512
#define KK 32
#define FULL 0xFFFFFFFFu
#define NEG_INF (-3.402823466e+38f)

// Schedule: batch indices sorted by descending sequence length (LPT).
__device__ unsigned short g_sched[BB];

// ---------------------------------------------------------------------------
// Pre-pass: counting sort of batch indices by descending length.
// ---------------------------------------------------------------------------
__global__ __launch_bounds__(512)
void sched_kernel(const int* __restrict__ lens)
{
    __shared__ int h[TT + 1];
    __shared__ int sc[TT];
    __shared__ int ctr[TT + 1];

    const int tid = threadIdx.x;

    h[tid] = 0;
    if (tid == 0) h[TT] = 0;
    __syncthreads();

    for (int b = tid; b < BB; b += 512) atomicAdd(&h[lens[b]], 1);
    __syncthreads();

    const int r = tid;
    const int v = h[TT - r];
    sc[r] = v;
    __syncthreads();
#pragma unroll
    for (int d = 1; d < TT; d <<= 1) {
        const int add = (r >= d) ? sc[r - d] : 0;
        __syncthreads();
        sc[r] += add;
        __syncthreads();
    }
    ctr[TT - r] = sc[r] - v;
    __syncthreads();

    for (int b = tid; b < BB; b += 512) {
        const int pos = atomicAdd(&ctr[lens[b]], 1);
        g_sched[pos] = (unsigned short)b;
    }
}

// ---------------------------------------------------------------------------
// Main kernel: one block = 64 threads = 2 warps = 2 batch elements.
// Each warp runs BOTH recurrences (Viterbi + logsumexp) for its job.
// Backpointers are bit-packed via ballots: 5 uint32 words per step
// (bit 'lane' of word j = bit j of that lane's backpointer) -> 20B/step,
// cutting smem from 39KB to 26KB per block => 7 blocks/SM instead of 5.
// ---------------------------------------------------------------------------
__global__ __launch_bounds__(64, 7)
void crf_kernel(const float* __restrict__ pot,
                const float* __restrict__ trans,
                const int*   __restrict__ lens,
                const int*   __restrict__ tags_in,
                float*       __restrict__ out)
{
    __shared__ float s_trans[KK * KK];                     // 4 KB
    __shared__ __align__(16) float2 s_ab[2][2][KK];        // [warp][buf][lane]=(alpha,e)
    __shared__ unsigned int s_bpw[2][TT][5];               // 20 KB packed backpointers
    __shared__ unsigned char s_tg[2][TT];                  // decoded tags

    const int tid  = threadIdx.x;
    const int lane = tid & 31;
    const int w    = tid >> 5;
    const int b    = g_sched[blockIdx.x * 2 + w];          // LPT: adjacent lengths pair

    for (int i = tid; i < KK * KK; i += 64) s_trans[i] = trans[i];
    __syncthreads();

    const float* potb = pot + (size_t)b * TT * KK;
    const int len = lens[b];

    // Per-lane transition column (kcur = lane) and its exp
    float tcol[KK];
    float ecol[KK];
#pragma unroll
    for (int i = 0; i < KK; ++i) {
        tcol[i] = s_trans[i * KK + lane];
        ecol[i] = expf(tcol[i]);
    }

    float alpha = potb[lane];   // Viterbi state
    float beta  = alpha;        // logsumexp state

    // 4-deep prefetch pipeline for the single shared pot stream
    float p0 = potb[(size_t)1 * KK + lane];
    float p1 = potb[(size_t)2 * KK + lane];
    float p2 = potb[(size_t)3 * KK + lane];
    float p3 = potb[(size_t)4 * KK + lane];

#pragma unroll 2
    for (int t = 1; t < len; ++t) {
        const float ptc = p0;
        p0 = p1; p1 = p2; p2 = p3;
        int tn = t + 4; tn = (tn < TT) ? tn : TT - 1;
        p3 = potb[(size_t)tn * KK + lane];

        // stabilizer: warp-uniform lane-0 beta (within ~12 of warp max ->
        // exp(beta-m) <= e^12, no overflow, negligible error)
        const float m = __shfl_sync(FULL, beta, 0);
        const float e = __expf(beta - m);

        float2* sab = &s_ab[w][t & 1][0];
        sab[lane] = make_float2(alpha, e);
        __syncwarp();
        const float4* sv = (const float4*)sab;   // sv[j] = {a2j, e2j, a2j+1, e2j+1}

        // Viterbi: 4 blocked argmax chains; lse: 4 blocked fma chains
        float bv0 = NEG_INF, bv1 = NEG_INF, bv2 = NEG_INF, bv3 = NEG_INF;
        int   bi0 = 0, bi1 = 0, bi2 = 0, bi3 = 0;
        float a0 = 0.f, a1 = 0.f, a2 = 0.f, a3 = 0.f;
#pragma unroll
        for (int j = 0; j < 16; ++j) {
            const float4 v4 = sv[j];
            const int kb = j * 2;
            const float s0 = v4.x + tcol[kb + 0];
            const float s1 = v4.z + tcol[kb + 1];
            const float pr = fmaf(v4.y, ecol[kb + 0], v4.w * ecol[kb + 1]);
            if ((j >> 2) == 0) {
                if (s0 > bv0) { bv0 = s0; bi0 = kb + 0; }
                if (s1 > bv0) { bv0 = s1; bi0 = kb + 1; }
                a0 += pr;
            } else if ((j >> 2) == 1) {
                if (s0 > bv1) { bv1 = s0; bi1 = kb + 0; }
                if (s1 > bv1) { bv1 = s1; bi1 = kb + 1; }
                a1 += pr;
            } else if ((j >> 2) == 2) {
                if (s0 > bv2) { bv2 = s0; bi2 = kb + 0; }
                if (s1 > bv2) { bv2 = s1; bi2 = kb + 1; }
                a2 += pr;
            } else {
                if (s0 > bv3) { bv3 = s0; bi3 = kb + 0; }
                if (s1 > bv3) { bv3 = s1; bi3 = kb + 1; }
                a3 += pr;
            }
        }
        // combine in ascending-kp order with strict > : exact first-index tie-break
        float best = bv0; int bk = bi0;
        if (bv1 > best) { best = bv1; bk = bi1; }
        if (bv2 > best) { best = bv2; bk = bi2; }
        if (bv3 > best) { best = bv3; bk = bi3; }

        alpha = ptc + best;
        beta  = ptc + m + __logf((a0 + a1) + (a2 + a3));

        // bit-pack the warp's 32 backpointers: word j holds bit j of every lane
        const unsigned int w0 = __ballot_sync(FULL, bk & 1);
        const unsigned int w1 = __ballot_sync(FULL, bk & 2);
        const unsigned int w2 = __ballot_sync(FULL, bk & 4);
        const unsigned int w3 = __ballot_sync(FULL, bk & 8);
        const unsigned int w4 = __ballot_sync(FULL, bk & 16);
        unsigned int wsel = w0;
        if (lane == 1) wsel = w1;
        if (lane == 2) wsel = w2;
        if (lane == 3) wsel = w3;
        if (lane == 4) wsel = w4;
        if (lane < 5) s_bpw[w][t][lane] = wsel;
    }

    // ---- Viterbi epilogue: warp argmax over lanes (first index on ties) ----
    float bs = alpha;
    int   bt = lane;
#pragma unroll
    for (int o = 16; o > 0; o >>= 1) {
        const float ov = __shfl_xor_sync(FULL, bs, o);
        const int   oi = __shfl_xor_sync(FULL, bt, o);
        if (ov > bs || (ov == bs && oi < bt)) { bs = ov; bt = oi; }
    }

    __syncwarp();   // all packed bp writes visible to lane 0
    if (lane == 0) {
        unsigned char* st = s_tg[w];
        int carry = bt;
        for (int t = TT - 1; t >= len - 1; --t) st[t] = (unsigned char)carry;
        for (int t = len - 1; t >= 1; --t) {
            const unsigned int* bw = s_bpw[w][t];
            const int c = carry;
            carry = (int)(((bw[0] >> c) & 1u)
                        | (((bw[1] >> c) & 1u) << 1)
                        | (((bw[2] >> c) & 1u) << 2)
                        | (((bw[3] >> c) & 1u) << 3)
                        | (((bw[4] >> c) & 1u) << 4));
            st[t - 1] = (unsigned char)carry;
        }
    }
    __syncwarp();

    // outputs: tags [B*T] (coalesced), best_score [B]
    for (int t = lane; t < TT; t += 32)
        out[(size_t)b * TT + t] = (float)s_tg[w][t];
    if (lane == 0)
        out[(size_t)BB * TT + b] = bs;

    // ---- lse epilogue: log_norm (full-precision lane reduce) ----
    float m2 = beta;
#pragma unroll
    for (int o = 16; o > 0; o >>= 1)
        m2 = fmaxf(m2, __shfl_xor_sync(FULL, m2, o));
    float s2 = __expf(beta - m2);
#pragma unroll
    for (int o = 16; o > 0; o >>= 1)
        s2 += __shfl_xor_sync(FULL, s2, o);
    const float logZ = m2 + logf(s2);

    // sequence score: unary (t < len) + binary (t < len-1)
    const int* tagb = tags_in + (size_t)b * TT;
    float ss = 0.0f;
    for (int t = lane; t < TT; t += 32) {
        const int tg = tagb[t];
        if (t < len)     ss += potb[(size_t)t * KK + tg];
        if (t + 1 < len) ss += s_trans[tg * KK + tagb[t + 1]];
    }
#pragma unroll
    for (int o = 16; o > 0; o >>= 1)
        ss += __shfl_xor_sync(FULL, ss, o);

    if (lane == 0)
        out[(size_t)BB * TT + BB + b] = ss - logZ;
}

extern "C" void kernel_launch(void* const* d_in, const int* in_sizes, int n_in,
                              void* d_out, int out_size)
{
    const float* potentials       = (const float*)d_in[0];
    const float* transitions      = (const float*)d_in[1];
    const int*   sequence_lengths = (const int*)d_in[2];
    const int*   tag_indices      = (const int*)d_in[3];
    float*       out              = (float*)d_out;

    sched_kernel<<<1, 512>>>(sequence_lengths);
    crf_kernel<<<BB / 2, 64>>>(potentials, transitions, sequence_lengths,
                               tag_indices, out);
}

// round 15
// speedup vs baseline: 1.2806x; 1.2806x over previous
#include <cuda_runtime.h>
#include <cstdint>

#define BB 2048
#define TT 512
#define KK 32
#define FULL 0xFFFFFFFFu
#define NEG_INF (-3.402823466e+38f)

// Schedule: batch indices sorted by descending sequence length (LPT).
__device__ unsigned short g_sched[BB];

// ---------------------------------------------------------------------------
// Pre-pass: counting sort of batch indices by descending length.
// ---------------------------------------------------------------------------
__global__ __launch_bounds__(512)
void sched_kernel(const int* __restrict__ lens)
{
    __shared__ int h[TT + 1];
    __shared__ int sc[TT];
    __shared__ int ctr[TT + 1];

    const int tid = threadIdx.x;

    h[tid] = 0;
    if (tid == 0) h[TT] = 0;
    __syncthreads();

    for (int b = tid; b < BB; b += 512) atomicAdd(&h[lens[b]], 1);
    __syncthreads();

    const int r = tid;
    const int v = h[TT - r];
    sc[r] = v;
    __syncthreads();
#pragma unroll
    for (int d = 1; d < TT; d <<= 1) {
        const int add = (r >= d) ? sc[r - d] : 0;
        __syncthreads();
        sc[r] += add;
        __syncthreads();
    }
    ctr[TT - r] = sc[r] - v;
    __syncthreads();

    for (int b = tid; b < BB; b += 512) {
        const int pos = atomicAdd(&ctr[lens[b]], 1);
        g_sched[pos] = (unsigned short)b;
    }
}

// ---------------------------------------------------------------------------
// Main kernel: one block = 64 threads = 2 warps = 2 batch elements.
// Each warp runs BOTH recurrences for its job:
//  - Viterbi in log domain (exact, tie-break preserved)
//  - partition function in EXP domain: u_t = exp(pt) * (u_{t-1} . expT),
//    with power-of-two rescaling every 2 steps (exact; integer exponent
//    accumulator). No logf on the per-step chain; exp(pt) is off-chain.
// ---------------------------------------------------------------------------
__global__ __launch_bounds__(64)
void crf_kernel(const float* __restrict__ pot,
                const float* __restrict__ trans,
                const int*   __restrict__ lens,
                const int*   __restrict__ tags_in,
                float*       __restrict__ out)
{
    __shared__ float s_trans[KK * KK];                     // 4 KB
    __shared__ __align__(16) float2 s_ab[2][2][KK];        // [warp][buf][lane]=(alpha,u)
    __shared__ unsigned char s_bp[2][TT][KK];              // 32 KB backpointers
    __shared__ unsigned char s_tg[2][TT];                  // decoded tags

    const int tid  = threadIdx.x;
    const int lane = tid & 31;
    const int w    = tid >> 5;
    const int b    = g_sched[blockIdx.x * 2 + w];          // LPT: adjacent lengths pair

    for (int i = tid; i < KK * KK; i += 64) s_trans[i] = trans[i];
    __syncthreads();

    const float* potb = pot + (size_t)b * TT * KK;
    const int len = lens[b];

    // Per-lane transition column (kcur = lane) and its exp
    float tcol[KK];
    float ecol[KK];
#pragma unroll
    for (int i = 0; i < KK; ++i) {
        tcol[i] = s_trans[i * KK + lane];
        ecol[i] = expf(tcol[i]);
    }

    const float pot0 = potb[lane];
    float alpha = pot0;                                    // Viterbi state (log domain)
    const float c0 = __shfl_sync(FULL, pot0, 0);           // constant log-offset
    float u = __expf(pot0 - c0);                           // exp-domain lse state
    int   E_acc = 0;                                       // power-of-two rescale exponent

    // 4-deep prefetch pipeline for the single shared pot stream
    float p0 = potb[(size_t)1 * KK + lane];
    float p1 = potb[(size_t)2 * KK + lane];
    float p2 = potb[(size_t)3 * KK + lane];
    float p3 = potb[(size_t)4 * KK + lane];

#pragma unroll 2
    for (int t = 1; t < len; ++t) {
        const float ptc = p0;
        p0 = p1; p1 = p2; p2 = p3;
        int tn = t + 4; tn = (tn < TT) ? tn : TT - 1;
        p3 = potb[(size_t)tn * KK + lane];

        // off-critical-path: only depends on the (prefetched) potential
        const float ep = __expf(ptc);

        float2* sab = &s_ab[w][t & 1][0];
        sab[lane] = make_float2(alpha, u);
        __syncwarp();
        const float4* sv = (const float4*)sab;   // sv[j] = {a2j, u2j, a2j+1, u2j+1}

        // Viterbi: 4 blocked argmax chains; lse: 4 blocked fma chains
        float bv0 = NEG_INF, bv1 = NEG_INF, bv2 = NEG_INF, bv3 = NEG_INF;
        int   bi0 = 0, bi1 = 0, bi2 = 0, bi3 = 0;
        float a0 = 0.f, a1 = 0.f, a2 = 0.f, a3 = 0.f;
#pragma unroll
        for (int j = 0; j < 16; ++j) {
            const float4 v4 = sv[j];
            const int kb = j * 2;
            const float s0 = v4.x + tcol[kb + 0];
            const float s1 = v4.z + tcol[kb + 1];
            const float pr = fmaf(v4.y, ecol[kb + 0], v4.w * ecol[kb + 1]);
            if ((j >> 2) == 0) {
                if (s0 > bv0) { bv0 = s0; bi0 = kb + 0; }
                if (s1 > bv0) { bv0 = s1; bi0 = kb + 1; }
                a0 += pr;
            } else if ((j >> 2) == 1) {
                if (s0 > bv1) { bv1 = s0; bi1 = kb + 0; }
                if (s1 > bv1) { bv1 = s1; bi1 = kb + 1; }
                a1 += pr;
            } else if ((j >> 2) == 2) {
                if (s0 > bv2) { bv2 = s0; bi2 = kb + 0; }
                if (s1 > bv2) { bv2 = s1; bi2 = kb + 1; }
                a2 += pr;
            } else {
                if (s0 > bv3) { bv3 = s0; bi3 = kb + 0; }
                if (s1 > bv3) { bv3 = s1; bi3 = kb + 1; }
                a3 += pr;
            }
        }
        // combine in ascending-kp order with strict > : exact first-index tie-break
        float best = bv0; int bk = bi0;
        if (bv1 > best) { best = bv1; bk = bi1; }
        if (bv2 > best) { best = bv2; bk = bi2; }
        if (bv3 > best) { best = bv3; bk = bi3; }

        alpha = ptc + best;
        u = ep * ((a0 + a1) + (a2 + a3));

        // power-of-two rescale every 2 steps: keeps u in fp32 range exactly
        if ((t & 1) == 0) {
            const float u0 = __shfl_sync(FULL, u, 0);
            const int E = ((__float_as_int(u0) >> 23) & 0xFF) - 127;
            u *= __int_as_float((127 - E) << 23);
            E_acc += E;
        }

        s_bp[w][t][lane] = (unsigned char)bk;
    }

    // ---- Viterbi epilogue: warp argmax over lanes (first index on ties) ----
    float bs = alpha;
    int   bt = lane;
#pragma unroll
    for (int o = 16; o > 0; o >>= 1) {
        const float ov = __shfl_xor_sync(FULL, bs, o);
        const int   oi = __shfl_xor_sync(FULL, bt, o);
        if (ov > bs || (ov == bs && oi < bt)) { bs = ov; bt = oi; }
    }

    __syncwarp();   // all s_bp writes visible to lane 0
    if (lane == 0) {
        unsigned char* st = s_tg[w];
        int carry = bt;
        for (int t = TT - 1; t >= len - 1; --t) st[t] = (unsigned char)carry;
        for (int t = len - 1; t >= 1; --t) {
            carry = s_bp[w][t][carry];
            st[t - 1] = (unsigned char)carry;
        }
    }
    __syncwarp();

    // outputs: tags [B*T] (coalesced), best_score [B]
    for (int t = lane; t < TT; t += 32)
        out[(size_t)b * TT + t] = (float)s_tg[w][t];
    if (lane == 0)
        out[(size_t)BB * TT + b] = bs;

    // ---- lse epilogue: logZ = log(sum_lanes u) + E_acc*ln2 + c0 ----
    float s2 = u;
#pragma unroll
    for (int o = 16; o > 0; o >>= 1)
        s2 += __shfl_xor_sync(FULL, s2, o);
    const float logZ = logf(s2) + (float)((double)E_acc * 0.6931471805599453) + c0;

    // sequence score: unary (t < len) + binary (t < len-1)
    const int* tagb = tags_in + (size_t)b * TT;
    float ss = 0.0f;
    for (int t = lane; t < TT; t += 32) {
        const int tg = tagb[t];
        if (t < len)     ss += potb[(size_t)t * KK + tg];
        if (t + 1 < len) ss += s_trans[tg * KK + tagb[t + 1]];
    }
#pragma unroll
    for (int o = 16; o > 0; o >>= 1)
        ss += __shfl_xor_sync(FULL, ss, o);

    if (lane == 0)
        out[(size_t)BB * TT + BB + b] = ss - logZ;
}

extern "C" void kernel_launch(void* const* d_in, const int* in_sizes, int n_in,
                              void* d_out, int out_size)
{
    const float* potentials       = (const float*)d_in[0];
    const float* transitions      = (const float*)d_in[1];
    const int*   sequence_lengths = (const int*)d_in[2];
    const int*   tag_indices      = (const int*)d_in[3];
    float*       out              = (float*)d_out;

    sched_kernel<<<1, 512>>>(sequence_lengths);
    crf_kernel<<<BB / 2, 64>>>(potentials, transitions, sequence_lengths,
                               tag_indices, out);
}